// round 2
// baseline (speedup 1.0000x reference)
#include <cuda_runtime.h>
#include <cstdint>
#include <cstddef>

#define NN 8192
#define IN_DIM 256
#define OUT_DIM 64
#define ALPHA 0.2f

#define CB 8            // column chunks (grid.x)
#define NR 256          // rows per block
#define CT 64           // columns per tile
#define PITCH 68        // smem pitch for w tile (bank-conflict free, 16B-aligned)
#define TILES 16        // (8192 / CB) / CT
#define COLS_PER_BLOCK (NN / CB)

// -------- device scratch (static: no allocations allowed) --------
__device__ float g_Wh[(size_t)NN * OUT_DIM];
__device__ float g_f1[NN];
__device__ float g_f2[NN];
__device__ float g_num[(size_t)CB * NN * OUT_DIM];   // ~16.8 MB
__device__ float g_den[CB * NN];

typedef unsigned long long ull;

__device__ __forceinline__ ull pk2(float w) {
    ull r; asm("mov.b64 %0, {%1, %1};" : "=l"(r) : "f"(w)); return r;
}
__device__ __forceinline__ ull fma2(ull a, ull b, ull c) {
    ull d; asm("fma.rn.f32x2 %0, %1, %2, %3;" : "=l"(d) : "l"(a), "l"(b), "l"(c)); return d;
}
__device__ __forceinline__ float2 unpk(ull v) {
    float2 f; asm("mov.b64 {%0, %1}, %2;" : "=f"(f.x), "=f"(f.y) : "l"(v)); return f;
}

// ================= K1: Wh = h@W, f1 = Wh@a1, f2 = Wh@a2 =================
__global__ void k1_wh(const float* __restrict__ h, const float* __restrict__ W,
                      const float* __restrict__ a) {
    __shared__ float hs[4][IN_DIM];
    __shared__ float red[2][4][OUT_DIM];
    int tid = threadIdx.x;
    int k = tid & 63, rg = tid >> 6;          // 4 rows x 64 cols
    int row0 = blockIdx.x * 4;

    for (int t = tid; t < 4 * IN_DIM; t += 256)
        hs[t >> 8][t & 255] = h[(size_t)(row0 + (t >> 8)) * IN_DIM + (t & 255)];
    __syncthreads();

    float acc = 0.f;
#pragma unroll 8
    for (int i = 0; i < IN_DIM; i++)
        acc = fmaf(hs[rg][i], W[i * OUT_DIM + k], acc);

    g_Wh[(size_t)(row0 + rg) * OUT_DIM + k] = acc;
    red[0][rg][k] = acc * a[k];
    red[1][rg][k] = acc * a[OUT_DIM + k];
    __syncthreads();

    if (tid < 8) {
        int which = tid >> 2, r = tid & 3;
        float s = 0.f;
#pragma unroll
        for (int j = 0; j < OUT_DIM; j++) s += red[which][r][j];
        if (which == 0) g_f1[row0 + r] = s;
        else            g_f2[row0 + r] = s;
    }
}

// ================= K2: masked-softmax attention (unnormalized) =================
// Each block: 256 rows x 1024 cols. Per 64-col tile:
//   stage 1: w[r][j] = A>0 ? exp(lrelu(f1_r + f2_j)) : 0   (coalesced int4 A loads)
//   stage 2: acc[r][k] += w * Wh[j][k] via packed fma.rn.f32x2 (FFMA2)
extern __shared__ float k2_smem[];

__global__ void __launch_bounds__(256, 2) k2_attn(const int* __restrict__ A) {
    float* wS  = k2_smem;                 // NR * PITCH floats
    float* whS = k2_smem + NR * PITCH;    // CT * OUT_DIM floats

    int tid = threadIdx.x;
    int kq = tid & 3;                     // 16-wide k slice
    int rg = tid >> 2;                    // 0..63 ; rows rg + {0,64,128,192}
    int rowBase = blockIdx.y * NR;
    int colBase = blockIdx.x * COLS_PER_BLOCK;

    ull acc[4][8];
#pragma unroll
    for (int m = 0; m < 4; m++)
#pragma unroll
        for (int p = 0; p < 8; p++) acc[m][p] = 0ULL;
    float dn[4] = {0.f, 0.f, 0.f, 0.f};

    for (int tile = 0; tile < TILES; ++tile) {
        int c0 = colBase + tile * CT;
        __syncthreads();   // previous stage-2 reads done before overwriting smem

        // load Wh tile [CT][64] (contiguous 16 KB)
        const float4* src = (const float4*)(g_Wh + (size_t)c0 * OUT_DIM);
        float4* dst = (float4*)whS;
#pragma unroll
        for (int t = 0; t < 4; t++) dst[t * 256 + tid] = src[t * 256 + tid];

        // ---- stage 1: compute w tile ----
#pragma unroll 4
        for (int it = 0; it < 16; ++it) {
            int lin = it * 256 + tid;          // int4 index in 256x(64/4)
            int r = lin >> 4;
            int jj = (lin & 15) << 2;
            const int4 a4 = *(const int4*)(A + (size_t)(rowBase + r) * NN + c0 + jj);
            float f1v = g_f1[rowBase + r];
            float4 f2v = *(const float4*)(g_f2 + c0 + jj);
            float4 wv;
            float s0 = f1v + f2v.x, s1 = f1v + f2v.y, s2 = f1v + f2v.z, s3 = f1v + f2v.w;
            wv.x = (a4.x > 0) ? __expf(fmaxf(s0, ALPHA * s0)) : 0.f;
            wv.y = (a4.y > 0) ? __expf(fmaxf(s1, ALPHA * s1)) : 0.f;
            wv.z = (a4.z > 0) ? __expf(fmaxf(s2, ALPHA * s2)) : 0.f;
            wv.w = (a4.w > 0) ? __expf(fmaxf(s3, ALPHA * s3)) : 0.f;
            *(float4*)(wS + r * PITCH + jj) = wv;
        }
        __syncthreads();

        // ---- stage 2: rank-update with packed f32x2 FMA ----
#pragma unroll 4
        for (int j = 0; j < CT; ++j) {
            float w0 = wS[(rg      ) * PITCH + j];
            float w1 = wS[(rg +  64) * PITCH + j];
            float w2 = wS[(rg + 128) * PITCH + j];
            float w3 = wS[(rg + 192) * PITCH + j];
            dn[0] += w0; dn[1] += w1; dn[2] += w2; dn[3] += w3;
            ull wp0 = pk2(w0), wp1 = pk2(w1), wp2 = pk2(w2), wp3 = pk2(w3);
            const ulonglong2* whp = (const ulonglong2*)(whS + j * OUT_DIM + (kq << 4));
            ulonglong2 q0 = whp[0], q1 = whp[1], q2 = whp[2], q3 = whp[3];
            ull b[8] = {q0.x, q0.y, q1.x, q1.y, q2.x, q2.y, q3.x, q3.y};
#pragma unroll
            for (int p = 0; p < 8; p++) {
                acc[0][p] = fma2(wp0, b[p], acc[0][p]);
                acc[1][p] = fma2(wp1, b[p], acc[1][p]);
                acc[2][p] = fma2(wp2, b[p], acc[2][p]);
                acc[3][p] = fma2(wp3, b[p], acc[3][p]);
            }
        }
    }

    // epilogue: write column-chunk partials
    size_t cbase = (size_t)blockIdx.x * NN;
#pragma unroll
    for (int m = 0; m < 4; m++) {
        int r = rowBase + rg + m * 64;
        float* np = g_num + (cbase + r) * OUT_DIM + (kq << 4);
#pragma unroll
        for (int p = 0; p < 8; p++) {
            float2 f = unpk(acc[m][p]);
            np[2 * p]     = f.x;
            np[2 * p + 1] = f.y;
        }
        if (kq == 0) g_den[cbase + r] = dn[m];
    }
}

// ================= K3: reduce partials, normalize, elu =================
__global__ void k3_fin(float* __restrict__ out) {
    int gid = blockIdx.x * 256 + threadIdx.x;   // over N*OUT_DIM
    int row = gid >> 6;
    float s = 0.f, d = 0.f;
#pragma unroll
    for (int c = 0; c < CB; c++) s += g_num[(size_t)c * NN * OUT_DIM + gid];
#pragma unroll
    for (int c = 0; c < CB; c++) d += g_den[c * NN + row];
    float v = s / d;
    out[gid] = v > 0.f ? v : expm1f(v);
}

// ================= launch =================
extern "C" void kernel_launch(void* const* d_in, const int* in_sizes, int n_in,
                              void* d_out, int out_size) {
    // identify inputs by element count (robust to ordering)
    const float* h = nullptr; const int* A = nullptr;
    const float* W = nullptr; const float* a = nullptr;
    for (int i = 0; i < n_in; i++) {
        if      (in_sizes[i] == NN * IN_DIM)      h = (const float*)d_in[i];
        else if (in_sizes[i] == NN * NN / 1)      A = (const int*)d_in[i];
        else if (in_sizes[i] == IN_DIM * OUT_DIM) W = (const float*)d_in[i];
        else if (in_sizes[i] == 2 * OUT_DIM)      a = (const float*)d_in[i];
    }
    float* out = (float*)d_out;

    const int k2_smem_bytes = (NR * PITCH + CT * OUT_DIM) * (int)sizeof(float); // 86016
    cudaFuncSetAttribute(k2_attn, cudaFuncAttributeMaxDynamicSharedMemorySize, k2_smem_bytes);

    k1_wh<<<NN / 4, 256>>>(h, W, a);
    dim3 g2(CB, NN / NR);
    k2_attn<<<g2, 256, k2_smem_bytes>>>(A);
    k3_fin<<<(NN * OUT_DIM) / 256, 256>>>(out);
}

// round 4
// speedup vs baseline: 2.7317x; 2.7317x over previous
#include <cuda_runtime.h>
#include <cuda_fp16.h>
#include <cstdint>
#include <cstddef>

#define NN 8192
#define OUT_DIM 64
#define IN_DIM 256
#define KB 4                  // K-split across grid.x
#define KSLAB (NN / KB)       // 2048
#define MTILE 128             // rows per CTA

// ---------------- device scratch ----------------
__device__ float g_Wh[(size_t)NN * OUT_DIM];
__device__ float g_f1[NN];
__device__ float g_f2[NN];
__device__ float g_LS;                       // log of global scale
__device__ float2 g_EG1[NN];                 // {S*exp(f1), S*exp(0.2 f1)}
__device__ float2 g_EG2[NN];                 // {exp(f2), exp(0.2 f2)}
__device__ uint4 g_Bfrag[512 * 4 * 32];      // Wh in fp16 mma-B-fragment layout (1 MB)
__device__ float g_num[(size_t)KB * NN * OUT_DIM];
__device__ float g_den[KB * NN];

// ---------------- mma helper ----------------
__device__ __forceinline__ void mma16816(float* d, uint32_t a0, uint32_t a1,
                                         uint32_t a2, uint32_t a3,
                                         uint32_t b0, uint32_t b1) {
    asm volatile(
        "mma.sync.aligned.m16n8k16.row.col.f32.f16.f16.f32 "
        "{%0,%1,%2,%3},{%4,%5,%6,%7},{%8,%9},{%0,%1,%2,%3};"
        : "+f"(d[0]), "+f"(d[1]), "+f"(d[2]), "+f"(d[3])
        : "r"(a0), "r"(a1), "r"(a2), "r"(a3), "r"(b0), "r"(b1));
}
__device__ __forceinline__ uint32_t packh2(float lo, float hi) {
    __half2 h = __floats2half2_rn(lo, hi);   // x (lo bits) = first arg
    return *reinterpret_cast<uint32_t*>(&h);
}

// ================= K1: Wh = h@W, f1, f2 =================
// 128 blocks x 256 thr; 64 rows/block; W + h tile in smem.
extern __shared__ float k1sm[];
__global__ void k1_wh(const float* __restrict__ h, const float* __restrict__ W,
                      const float* __restrict__ a) {
    float* Ws = k1sm;                 // [256][64]
    float* hs = k1sm + IN_DIM * OUT_DIM;  // [64][260] padded
    int tid = threadIdx.x;
    int row = tid >> 2, cs = (tid & 3) * 16;
    int row0 = blockIdx.x * 64;

    for (int t = tid; t < IN_DIM * OUT_DIM; t += 256) Ws[t] = W[t];
    for (int t = tid; t < 64 * IN_DIM; t += 256)
        hs[(t >> 8) * 260 + (t & 255)] = h[((size_t)row0 << 8) + t];
    __syncthreads();

    float4 acc[4];
#pragma unroll
    for (int q = 0; q < 4; q++) acc[q] = make_float4(0.f, 0.f, 0.f, 0.f);

#pragma unroll 4
    for (int k = 0; k < IN_DIM; k++) {
        float hv = hs[row * 260 + k];
        const float4* wr = (const float4*)(Ws + k * OUT_DIM + cs);
#pragma unroll
        for (int q = 0; q < 4; q++) {
            float4 w4 = wr[q];
            acc[q].x = fmaf(hv, w4.x, acc[q].x);
            acc[q].y = fmaf(hv, w4.y, acc[q].y);
            acc[q].z = fmaf(hv, w4.z, acc[q].z);
            acc[q].w = fmaf(hv, w4.w, acc[q].w);
        }
    }

    float4* wout = (float4*)(g_Wh + (size_t)(row0 + row) * OUT_DIM + cs);
#pragma unroll
    for (int q = 0; q < 4; q++) wout[q] = acc[q];

    float s1 = 0.f, s2 = 0.f;
#pragma unroll
    for (int q = 0; q < 4; q++) {
        const float* ap = a + cs + q * 4;
        const float* bp = a + OUT_DIM + cs + q * 4;
        float v[4] = {acc[q].x, acc[q].y, acc[q].z, acc[q].w};
#pragma unroll
        for (int c = 0; c < 4; c++) { s1 = fmaf(v[c], ap[c], s1); s2 = fmaf(v[c], bp[c], s2); }
    }
    s1 += __shfl_xor_sync(~0u, s1, 1); s1 += __shfl_xor_sync(~0u, s1, 2);
    s2 += __shfl_xor_sync(~0u, s2, 1); s2 += __shfl_xor_sync(~0u, s2, 2);
    if ((tid & 3) == 0) { g_f1[row0 + row] = s1; g_f2[row0 + row] = s2; }
}

// ========== K1max: global scale so that max w ~= 49000 (fp16-safe) ==========
__global__ void k1max(void) {
    __shared__ float m1s[8], m2s[8];
    int tid = threadIdx.x;
    float m1 = -1e30f, m2 = -1e30f;
    for (int i = tid; i < NN; i += 256) {
        m1 = fmaxf(m1, g_f1[i]);
        m2 = fmaxf(m2, g_f2[i]);
    }
#pragma unroll
    for (int o = 16; o; o >>= 1) {
        m1 = fmaxf(m1, __shfl_xor_sync(~0u, m1, o));
        m2 = fmaxf(m2, __shfl_xor_sync(~0u, m2, o));
    }
    if ((tid & 31) == 0) { m1s[tid >> 5] = m1; m2s[tid >> 5] = m2; }
    __syncthreads();
    if (tid == 0) {
        float a1 = m1s[0], a2 = m2s[0];
#pragma unroll
        for (int i = 1; i < 8; i++) { a1 = fmaxf(a1, m1s[i]); a2 = fmaxf(a2, m2s[i]); }
        g_LS = logf(49000.f) - a1 - a2;
    }
}

// ========== K1c: exp vectors ==========
__global__ void k1c_exp(void) {
    int i = blockIdx.x * 256 + threadIdx.x;
    float ls = g_LS;
    float f1 = g_f1[i], f2 = g_f2[i];
    g_EG1[i] = make_float2(expf(f1 + ls), expf(0.2f * f1 + ls));
    g_EG2[i] = make_float2(expf(f2), expf(0.2f * f2));
}

// ========== K1b: Wh -> fp16 mma-B-fragment layout ==========
__global__ void k1b_frag(void) {
    int kc = blockIdx.x;                  // 0..511
    int p = threadIdx.x >> 5, lane = threadIdx.x & 31;
    int k0 = kc * 16 + (lane & 3) * 2;
    int n0 = p * 16 + (lane >> 2);
    int n1 = n0 + 8;
    const float* w = g_Wh;
    uint4 o;
    o.x = packh2(w[(size_t)k0 * 64 + n0],       w[(size_t)(k0 + 1) * 64 + n0]);
    o.y = packh2(w[(size_t)(k0 + 8) * 64 + n0], w[(size_t)(k0 + 9) * 64 + n0]);
    o.z = packh2(w[(size_t)k0 * 64 + n1],       w[(size_t)(k0 + 1) * 64 + n1]);
    o.w = packh2(w[(size_t)(k0 + 8) * 64 + n1], w[(size_t)(k0 + 9) * 64 + n1]);
    g_Bfrag[(kc * 4 + p) * 32 + lane] = o;
}

// ================= K2: masked attention, HMMA rank-update =================
__global__ void __launch_bounds__(256, 2) k2_attn(const int* __restrict__ A) {
    __shared__ float2 EG2s[KSLAB];        // 16 KB
    __shared__ int As[8][16 * 36];        // per-warp A stage, 18 KB

    int tid = threadIdx.x, wid = tid >> 5, lane = tid & 31;
    int kb = blockIdx.x;
    int rowBase = blockIdx.y * MTILE;

    for (int i = tid; i < KSLAB; i += 256) EG2s[i] = g_EG2[kb * KSLAB + i];
    __syncthreads();

    int r_lo = lane >> 2;
    int q2 = (lane & 3) * 2;
    int myrow = rowBase + wid * 16;
    float2 eg1a = g_EG1[myrow + r_lo];
    float2 eg1b = g_EG1[myrow + r_lo + 8];

    float acc[8][4];
#pragma unroll
    for (int n = 0; n < 8; n++)
#pragma unroll
        for (int c = 0; c < 4; c++) acc[n][c] = 0.f;
    float dn0 = 0.f, dn1 = 0.f;

    const int* Arow = A + (size_t)myrow * NN + kb * KSLAB;
    int* Aw = As[wid];
    int ldRow = (lane >> 3), ldSeg = (lane & 7) * 4;

    for (int it = 0; it < KSLAB / 32; ++it) {
        int c32 = it * 32;
        __syncwarp();
        // stage A: 16 rows x 32 cols, fully coalesced 128B lines
#pragma unroll
        for (int L = 0; L < 4; L++) {
            int r = L * 4 + ldRow;
            int4 v = *(const int4*)(Arow + (size_t)r * NN + c32 + ldSeg);
            *(int4*)(Aw + r * 36 + ldSeg) = v;
        }
        __syncwarp();

#pragma unroll
        for (int ck = 0; ck < 2; ++ck) {
            int cl = c32 + ck * 16;
            float4 egA = *(const float4*)(&EG2s[cl + q2]);
            float4 egB = *(const float4*)(&EG2s[cl + q2 + 8]);
            int base = ck * 16 + q2;
            int2 aL0 = *(const int2*)(Aw + r_lo * 36 + base);
            int2 aL1 = *(const int2*)(Aw + r_lo * 36 + base + 8);
            int2 aH0 = *(const int2*)(Aw + (r_lo + 8) * 36 + base);
            int2 aH1 = *(const int2*)(Aw + (r_lo + 8) * 36 + base + 8);

            float w00 = (aL0.x > 0) ? fmaxf(eg1a.x * egA.x, eg1a.y * egA.y) : 0.f;
            float w01 = (aL0.y > 0) ? fmaxf(eg1a.x * egA.z, eg1a.y * egA.w) : 0.f;
            float w02 = (aL1.x > 0) ? fmaxf(eg1a.x * egB.x, eg1a.y * egB.y) : 0.f;
            float w03 = (aL1.y > 0) ? fmaxf(eg1a.x * egB.z, eg1a.y * egB.w) : 0.f;
            float w10 = (aH0.x > 0) ? fmaxf(eg1b.x * egA.x, eg1b.y * egA.y) : 0.f;
            float w11 = (aH0.y > 0) ? fmaxf(eg1b.x * egA.z, eg1b.y * egA.w) : 0.f;
            float w12 = (aH1.x > 0) ? fmaxf(eg1b.x * egB.x, eg1b.y * egB.y) : 0.f;
            float w13 = (aH1.y > 0) ? fmaxf(eg1b.x * egB.z, eg1b.y * egB.w) : 0.f;

            dn0 += (w00 + w01) + (w02 + w03);
            dn1 += (w10 + w11) + (w12 + w13);

            uint32_t a0 = packh2(w00, w01);
            uint32_t a1 = packh2(w10, w11);
            uint32_t a2 = packh2(w02, w03);
            uint32_t a3 = packh2(w12, w13);

            int kcg = (kb * KSLAB + cl) >> 4;
            const uint4* Bp = g_Bfrag + (size_t)kcg * 128 + lane;
#pragma unroll
            for (int p = 0; p < 4; ++p) {
                uint4 B4 = Bp[p * 32];
                mma16816(acc[2 * p],     a0, a1, a2, a3, B4.x, B4.y);
                mma16816(acc[2 * p + 1], a0, a1, a2, a3, B4.z, B4.w);
            }
        }
    }

    // denominator (fp32-exact)
    dn0 += __shfl_xor_sync(~0u, dn0, 1); dn0 += __shfl_xor_sync(~0u, dn0, 2);
    dn1 += __shfl_xor_sync(~0u, dn1, 1); dn1 += __shfl_xor_sync(~0u, dn1, 2);
    if ((lane & 3) == 0) {
        g_den[kb * NN + myrow + r_lo] = dn0;
        g_den[kb * NN + myrow + r_lo + 8] = dn1;
    }
    // numerator partials
    float* np = g_num + ((size_t)kb * NN + myrow) * OUT_DIM;
#pragma unroll
    for (int nt = 0; nt < 8; nt++) {
        int col = nt * 8 + q2;
        *(float2*)(np + (size_t)r_lo * OUT_DIM + col)       = make_float2(acc[nt][0], acc[nt][1]);
        *(float2*)(np + (size_t)(r_lo + 8) * OUT_DIM + col) = make_float2(acc[nt][2], acc[nt][3]);
    }
}

// ================= K3: reduce, normalize, elu =================
__global__ void k3_fin(float* __restrict__ out) {
    int gid = blockIdx.x * 256 + threadIdx.x;
    int row = gid >> 6;
    float s = 0.f, d = 0.f;
#pragma unroll
    for (int c = 0; c < KB; c++) s += g_num[(size_t)c * NN * OUT_DIM + gid];
#pragma unroll
    for (int c = 0; c < KB; c++) d += g_den[c * NN + row];
    float v = s / d;
    out[gid] = v > 0.f ? v : expm1f(v);
}

// ================= launch =================
extern "C" void kernel_launch(void* const* d_in, const int* in_sizes, int n_in,
                              void* d_out, int out_size) {
    const float* h = nullptr; const int* A = nullptr;
    const float* W = nullptr; const float* a = nullptr;
    for (int i = 0; i < n_in; i++) {
        if      (in_sizes[i] == NN * IN_DIM)      h = (const float*)d_in[i];
        else if (in_sizes[i] == IN_DIM * OUT_DIM) W = (const float*)d_in[i];
        else if (in_sizes[i] == 2 * OUT_DIM)      a = (const float*)d_in[i];
        else                                      A = (const int*)d_in[i];
    }
    float* out = (float*)d_out;

    const int k1_smem = (IN_DIM * OUT_DIM + 64 * 260) * (int)sizeof(float); // 132 KB
    cudaFuncSetAttribute(k1_wh, cudaFuncAttributeMaxDynamicSharedMemorySize, k1_smem);

    k1_wh<<<NN / 64, 256, k1_smem>>>(h, W, a);
    k1max<<<1, 256>>>();
    k1c_exp<<<NN / 256, 256>>>();
    k1b_frag<<<512, 128>>>();
    dim3 g2(KB, NN / MTILE);
    k2_attn<<<g2, 256>>>(A);
    k3_fin<<<(NN * OUT_DIM) / 256, 256>>>(out);
}

// round 5
// speedup vs baseline: 2.9283x; 1.0719x over previous
#include <cuda_runtime.h>
#include <cuda_fp16.h>
#include <cstdint>
#include <cstddef>

#define NN 8192
#define OUT_DIM 64
#define IN_DIM 256
#define KB 4                  // K-split across grid.x
#define KSLAB (NN / KB)       // 2048
#define MTILE 128             // rows per CTA
#define APITCH 68             // smem ints per staged A row

// ---------------- device scratch ----------------
__device__ float g_Wh[(size_t)NN * OUT_DIM];
__device__ float g_f1[NN];
__device__ float g_f2[NN];
__device__ float2 g_EG1[NN];                 // {S*exp(f1), S*exp(0.2 f1)}
__device__ float2 g_EG2[NN];                 // {exp(f2), exp(0.2 f2)}
__device__ uint4 g_Bfrag[512 * 4 * 32];      // Wh in fp16 mma-B-fragment layout (1 MB)
__device__ float g_num[(size_t)KB * NN * OUT_DIM];
__device__ float g_den[KB * NN];

// ---------------- mma helper ----------------
__device__ __forceinline__ void mma16816(float* d, uint32_t a0, uint32_t a1,
                                         uint32_t a2, uint32_t a3,
                                         uint32_t b0, uint32_t b1) {
    asm volatile(
        "mma.sync.aligned.m16n8k16.row.col.f32.f16.f16.f32 "
        "{%0,%1,%2,%3},{%4,%5,%6,%7},{%8,%9},{%0,%1,%2,%3};"
        : "+f"(d[0]), "+f"(d[1]), "+f"(d[2]), "+f"(d[3])
        : "r"(a0), "r"(a1), "r"(a2), "r"(a3), "r"(b0), "r"(b1));
}
__device__ __forceinline__ uint32_t packh2(float lo, float hi) {
    __half2 h = __floats2half2_rn(lo, hi);
    return *reinterpret_cast<uint32_t*>(&h);
}

// ================= K1: Wh = h@W, f1, f2 =================
extern __shared__ float k1sm[];
__global__ void k1_wh(const float* __restrict__ h, const float* __restrict__ W,
                      const float* __restrict__ a) {
    float* Ws = k1sm;                      // [256][64]
    float* hs = k1sm + IN_DIM * OUT_DIM;   // [64][260]
    int tid = threadIdx.x;
    int row = tid >> 2, cs = (tid & 3) * 16;
    int row0 = blockIdx.x * 64;

    for (int t = tid; t < IN_DIM * OUT_DIM; t += 256) Ws[t] = W[t];
    for (int t = tid; t < 64 * IN_DIM; t += 256)
        hs[(t >> 8) * 260 + (t & 255)] = h[((size_t)row0 << 8) + t];
    __syncthreads();

    float4 acc[4];
#pragma unroll
    for (int q = 0; q < 4; q++) acc[q] = make_float4(0.f, 0.f, 0.f, 0.f);

#pragma unroll 4
    for (int k = 0; k < IN_DIM; k++) {
        float hv = hs[row * 260 + k];
        const float4* wr = (const float4*)(Ws + k * OUT_DIM + cs);
#pragma unroll
        for (int q = 0; q < 4; q++) {
            float4 w4 = wr[q];
            acc[q].x = fmaf(hv, w4.x, acc[q].x);
            acc[q].y = fmaf(hv, w4.y, acc[q].y);
            acc[q].z = fmaf(hv, w4.z, acc[q].z);
            acc[q].w = fmaf(hv, w4.w, acc[q].w);
        }
    }

    float4* wout = (float4*)(g_Wh + (size_t)(row0 + row) * OUT_DIM + cs);
#pragma unroll
    for (int q = 0; q < 4; q++) wout[q] = acc[q];

    float s1 = 0.f, s2 = 0.f;
#pragma unroll
    for (int q = 0; q < 4; q++) {
        const float* ap = a + cs + q * 4;
        const float* bp = a + OUT_DIM + cs + q * 4;
        float v[4] = {acc[q].x, acc[q].y, acc[q].z, acc[q].w};
#pragma unroll
        for (int c = 0; c < 4; c++) { s1 = fmaf(v[c], ap[c], s1); s2 = fmaf(v[c], bp[c], s2); }
    }
    s1 += __shfl_xor_sync(~0u, s1, 1); s1 += __shfl_xor_sync(~0u, s1, 2);
    s2 += __shfl_xor_sync(~0u, s2, 1); s2 += __shfl_xor_sync(~0u, s2, 2);
    if ((tid & 3) == 0) { g_f1[row0 + row] = s1; g_f2[row0 + row] = s2; }
}

// ========== K1bc: blocks [0,256): B fragments; [256,288): exp vectors ==========
#define FRAG_BLOCKS 256
__global__ void __launch_bounds__(256) k1bc(void) {
    int bx = blockIdx.x, tid = threadIdx.x;

    if (bx < FRAG_BLOCKS) {
        // ---- frag part: 2 kc per block, smem-staged coalesced loads ----
        __shared__ float whs[2][16 * 64];
        int half = tid >> 7, t = tid & 127;
        int kc = bx * 2 + half;
        const float4* src = (const float4*)(g_Wh + (size_t)kc * 16 * 64);
        float4* dst = (float4*)whs[half];
        dst[t] = src[t];
        dst[t + 128] = src[t + 128];
        __syncthreads();

        int p = (t >> 5) & 3, lane = t & 31;
        int lk = (lane & 3) * 2;
        int n0 = p * 16 + (lane >> 2);
        int n1 = n0 + 8;
        const float* w = whs[half];
        uint4 o;
        o.x = packh2(w[lk * 64 + n0],       w[(lk + 1) * 64 + n0]);
        o.y = packh2(w[(lk + 8) * 64 + n0], w[(lk + 9) * 64 + n0]);
        o.z = packh2(w[lk * 64 + n1],       w[(lk + 1) * 64 + n1]);
        o.w = packh2(w[(lk + 8) * 64 + n1], w[(lk + 9) * 64 + n1]);
        g_Bfrag[(kc * 4 + p) * 32 + lane] = o;
    } else {
        // ---- exp part: redundant global max then 256 rows of exps ----
        __shared__ float m1s[8], m2s[8], lss;
        float m1 = -1e30f, m2 = -1e30f;
        for (int i = tid; i < NN; i += 256) {
            m1 = fmaxf(m1, g_f1[i]);
            m2 = fmaxf(m2, g_f2[i]);
        }
#pragma unroll
        for (int o = 16; o; o >>= 1) {
            m1 = fmaxf(m1, __shfl_xor_sync(~0u, m1, o));
            m2 = fmaxf(m2, __shfl_xor_sync(~0u, m2, o));
        }
        if ((tid & 31) == 0) { m1s[tid >> 5] = m1; m2s[tid >> 5] = m2; }
        __syncthreads();
        if (tid == 0) {
            float a1 = m1s[0], a2 = m2s[0];
#pragma unroll
            for (int i = 1; i < 8; i++) { a1 = fmaxf(a1, m1s[i]); a2 = fmaxf(a2, m2s[i]); }
            lss = logf(49000.f) - a1 - a2;
        }
        __syncthreads();
        float ls = lss;
        int i = (bx - FRAG_BLOCKS) * 256 + tid;
        float f1 = g_f1[i], f2 = g_f2[i];
        g_EG1[i] = make_float2(expf(f1 + ls), expf(0.2f * f1 + ls));
        g_EG2[i] = make_float2(expf(f2), expf(0.2f * f2));
    }
}

// ================= K2: masked attention, HMMA rank-update =================
// smem: EG2s (16 KB) + per-warp A stage (8 x 16 x APITCH ints)
extern __shared__ char k2smraw[];
__global__ void __launch_bounds__(256, 2) k2_attn(const int* __restrict__ A) {
    float2* EG2s = (float2*)k2smraw;                       // [KSLAB]
    int* AsBase = (int*)(k2smraw + KSLAB * sizeof(float2));

    int tid = threadIdx.x, wid = tid >> 5, lane = tid & 31;
    int kb = blockIdx.x;
    int rowBase = blockIdx.y * MTILE;

    for (int i = tid; i < KSLAB; i += 256) EG2s[i] = g_EG2[kb * KSLAB + i];
    __syncthreads();

    int r_lo = lane >> 2;
    int q2 = (lane & 3) * 2;
    int myrow = rowBase + wid * 16;
    float2 eg1a = g_EG1[myrow + r_lo];
    float2 eg1b = g_EG1[myrow + r_lo + 8];

    float acc[8][4];
#pragma unroll
    for (int n = 0; n < 8; n++)
#pragma unroll
        for (int c = 0; c < 4; c++) acc[n][c] = 0.f;
    float dn0 = 0.f, dn1 = 0.f;

    const int* Arow = A + (size_t)myrow * NN + kb * KSLAB;
    int* Aw = AsBase + wid * 16 * APITCH;
    int ldRow = lane >> 4;                 // 0..1
    int ldSeg = (lane & 15) * 4;           // 0..60

    // prologue prefetch (stage 0: cols [0,64))
    int4 pf[8];
#pragma unroll
    for (int L = 0; L < 8; L++)
        pf[L] = *(const int4*)(Arow + (size_t)(L * 2 + ldRow) * NN + ldSeg);

#pragma unroll 1
    for (int it = 0; it < KSLAB / 64; ++it) {
        // publish staged A
#pragma unroll
        for (int L = 0; L < 8; L++)
            *(int4*)(Aw + (L * 2 + ldRow) * APITCH + ldSeg) = pf[L];
        __syncwarp();

        // prefetch next stage while computing this one
        if (it + 1 < KSLAB / 64) {
            int cn = (it + 1) * 64;
#pragma unroll
            for (int L = 0; L < 8; L++)
                pf[L] = *(const int4*)(Arow + (size_t)(L * 2 + ldRow) * NN + cn + ldSeg);
        }

#pragma unroll
        for (int ck = 0; ck < 4; ++ck) {
            int cl = it * 64 + ck * 16;
            float4 egA = *(const float4*)(&EG2s[cl + q2]);
            float4 egB = *(const float4*)(&EG2s[cl + q2 + 8]);
            int base = ck * 16 + q2;
            int2 aL0 = *(const int2*)(Aw + r_lo * APITCH + base);
            int2 aL1 = *(const int2*)(Aw + r_lo * APITCH + base + 8);
            int2 aH0 = *(const int2*)(Aw + (r_lo + 8) * APITCH + base);
            int2 aH1 = *(const int2*)(Aw + (r_lo + 8) * APITCH + base + 8);

            float w00 = (aL0.x > 0) ? fmaxf(eg1a.x * egA.x, eg1a.y * egA.y) : 0.f;
            float w01 = (aL0.y > 0) ? fmaxf(eg1a.x * egA.z, eg1a.y * egA.w) : 0.f;
            float w02 = (aL1.x > 0) ? fmaxf(eg1a.x * egB.x, eg1a.y * egB.y) : 0.f;
            float w03 = (aL1.y > 0) ? fmaxf(eg1a.x * egB.z, eg1a.y * egB.w) : 0.f;
            float w10 = (aH0.x > 0) ? fmaxf(eg1b.x * egA.x, eg1b.y * egA.y) : 0.f;
            float w11 = (aH0.y > 0) ? fmaxf(eg1b.x * egA.z, eg1b.y * egA.w) : 0.f;
            float w12 = (aH1.x > 0) ? fmaxf(eg1b.x * egB.x, eg1b.y * egB.y) : 0.f;
            float w13 = (aH1.y > 0) ? fmaxf(eg1b.x * egB.z, eg1b.y * egB.w) : 0.f;

            dn0 += (w00 + w01) + (w02 + w03);
            dn1 += (w10 + w11) + (w12 + w13);

            uint32_t a0 = packh2(w00, w01);
            uint32_t a1 = packh2(w10, w11);
            uint32_t a2 = packh2(w02, w03);
            uint32_t a3 = packh2(w12, w13);

            int kcg = (kb * KSLAB + cl) >> 4;
            const uint4* Bp = g_Bfrag + (size_t)kcg * 128 + lane;
            uint4 B0 = Bp[0], B1 = Bp[32], B2 = Bp[64], B3 = Bp[96];
            mma16816(acc[0], a0, a1, a2, a3, B0.x, B0.y);
            mma16816(acc[1], a0, a1, a2, a3, B0.z, B0.w);
            mma16816(acc[2], a0, a1, a2, a3, B1.x, B1.y);
            mma16816(acc[3], a0, a1, a2, a3, B1.z, B1.w);
            mma16816(acc[4], a0, a1, a2, a3, B2.x, B2.y);
            mma16816(acc[5], a0, a1, a2, a3, B2.z, B2.w);
            mma16816(acc[6], a0, a1, a2, a3, B3.x, B3.y);
            mma16816(acc[7], a0, a1, a2, a3, B3.z, B3.w);
        }
        __syncwarp();
    }

    // denominator (fp32-exact)
    dn0 += __shfl_xor_sync(~0u, dn0, 1); dn0 += __shfl_xor_sync(~0u, dn0, 2);
    dn1 += __shfl_xor_sync(~0u, dn1, 1); dn1 += __shfl_xor_sync(~0u, dn1, 2);
    if ((lane & 3) == 0) {
        g_den[kb * NN + myrow + r_lo] = dn0;
        g_den[kb * NN + myrow + r_lo + 8] = dn1;
    }
    // numerator partials
    float* np = g_num + ((size_t)kb * NN + myrow) * OUT_DIM;
#pragma unroll
    for (int nt = 0; nt < 8; nt++) {
        int col = nt * 8 + q2;
        *(float2*)(np + (size_t)r_lo * OUT_DIM + col)       = make_float2(acc[nt][0], acc[nt][1]);
        *(float2*)(np + (size_t)(r_lo + 8) * OUT_DIM + col) = make_float2(acc[nt][2], acc[nt][3]);
    }
}

// ================= K3: reduce, normalize, elu (vectorized) =================
__global__ void k3_fin(float* __restrict__ out) {
    int gid = blockIdx.x * 256 + threadIdx.x;   // over (N*OUT_DIM)/4
    int base = gid * 4;
    int row = base >> 6;
    float4 s = make_float4(0.f, 0.f, 0.f, 0.f);
    float d = 0.f;
#pragma unroll
    for (int c = 0; c < KB; c++) {
        float4 v = *(const float4*)(g_num + (size_t)c * NN * OUT_DIM + base);
        s.x += v.x; s.y += v.y; s.z += v.z; s.w += v.w;
        d += g_den[c * NN + row];
    }
    float inv = 1.f / d;
    float4 o;
    o.x = s.x * inv; o.y = s.y * inv; o.z = s.z * inv; o.w = s.w * inv;
    o.x = o.x > 0.f ? o.x : expm1f(o.x);
    o.y = o.y > 0.f ? o.y : expm1f(o.y);
    o.z = o.z > 0.f ? o.z : expm1f(o.z);
    o.w = o.w > 0.f ? o.w : expm1f(o.w);
    *(float4*)(out + base) = o;
}

// ================= launch =================
extern "C" void kernel_launch(void* const* d_in, const int* in_sizes, int n_in,
                              void* d_out, int out_size) {
    const float* h = nullptr; const int* A = nullptr;
    const float* W = nullptr; const float* a = nullptr;
    for (int i = 0; i < n_in; i++) {
        if      (in_sizes[i] == NN * IN_DIM)      h = (const float*)d_in[i];
        else if (in_sizes[i] == IN_DIM * OUT_DIM) W = (const float*)d_in[i];
        else if (in_sizes[i] == 2 * OUT_DIM)      a = (const float*)d_in[i];
        else                                      A = (const int*)d_in[i];
    }
    float* out = (float*)d_out;

    const int k1_smem = (IN_DIM * OUT_DIM + 64 * 260) * (int)sizeof(float);
    cudaFuncSetAttribute(k1_wh, cudaFuncAttributeMaxDynamicSharedMemorySize, k1_smem);
    const int k2_smem = KSLAB * (int)sizeof(float2) + 8 * 16 * APITCH * (int)sizeof(int); // 51200
    cudaFuncSetAttribute(k2_attn, cudaFuncAttributeMaxDynamicSharedMemorySize, k2_smem);

    k1_wh<<<NN / 64, 256, k1_smem>>>(h, W, a);
    k1bc<<<FRAG_BLOCKS + NN / 256, 256>>>();
    dim3 g2(KB, NN / MTILE);
    k2_attn<<<g2, 256, k2_smem>>>(A);
    k3_fin<<<(NN * OUT_DIM) / 1024, 256>>>(out);
}

// round 6
// speedup vs baseline: 3.2959x; 1.1255x over previous
#include <cuda_runtime.h>
#include <cuda_fp16.h>
#include <cstdint>
#include <cstddef>

#define NN 8192
#define OUT_DIM 64
#define IN_DIM 256
#define KB 4                  // K-split across grid.x
#define KSLAB (NN / KB)       // 2048
#define MTILE 128             // rows per CTA
#define APITCH 68             // smem ints per staged A row
#define NIT (KSLAB / 64)      // 32 stages

// ---------------- device scratch ----------------
__device__ float g_Wh[(size_t)NN * OUT_DIM];
__device__ float g_f1[NN];
__device__ float g_f2[NN];
__device__ float2 g_EG1[NN];                 // {S*exp(f1), S*exp(0.2 f1)}
__device__ float2 g_EG2[NN];                 // {exp(f2), exp(0.2 f2)}
__device__ uint4 g_Bfrag[512 * 4 * 32];      // Wh in fp16 mma-B-fragment layout (1 MB)
__device__ float g_num[(size_t)KB * NN * OUT_DIM];
__device__ float g_den[KB * NN];

// ---------------- helpers ----------------
__device__ __forceinline__ void mma16816(float* d, uint32_t a0, uint32_t a1,
                                         uint32_t a2, uint32_t a3,
                                         uint32_t b0, uint32_t b1) {
    asm volatile(
        "mma.sync.aligned.m16n8k16.row.col.f32.f16.f16.f32 "
        "{%0,%1,%2,%3},{%4,%5,%6,%7},{%8,%9},{%0,%1,%2,%3};"
        : "+f"(d[0]), "+f"(d[1]), "+f"(d[2]), "+f"(d[3])
        : "r"(a0), "r"(a1), "r"(a2), "r"(a3), "r"(b0), "r"(b1));
}
__device__ __forceinline__ uint32_t packh2(float lo, float hi) {
    __half2 h = __floats2half2_rn(lo, hi);
    return *reinterpret_cast<uint32_t*>(&h);
}
__device__ __forceinline__ uint32_t s2u(const void* p) {
    uint32_t a;
    asm("{ .reg .u64 t; cvta.to.shared.u64 t, %1; cvt.u32.u64 %0, t; }" : "=r"(a) : "l"(p));
    return a;
}
__device__ __forceinline__ void cpasync16(uint32_t smem, const void* g) {
    asm volatile("cp.async.cg.shared.global [%0], [%1], 16;" :: "r"(smem), "l"(g) : "memory");
}
#define CP_COMMIT() asm volatile("cp.async.commit_group;" ::: "memory")
#define CP_WAIT1()  asm volatile("cp.async.wait_group 1;" ::: "memory")

// ================= K1: Wh = h@W, f1, f2 =================
extern __shared__ float k1sm[];
__global__ void k1_wh(const float* __restrict__ h, const float* __restrict__ W,
                      const float* __restrict__ a) {
    float* Ws = k1sm;                      // [256][64]
    float* hs = k1sm + IN_DIM * OUT_DIM;   // [64][260]
    int tid = threadIdx.x;
    int row = tid >> 2, cs = (tid & 3) * 16;
    int row0 = blockIdx.x * 64;

    for (int t = tid; t < IN_DIM * OUT_DIM; t += 256) Ws[t] = W[t];
    for (int t = tid; t < 64 * IN_DIM; t += 256)
        hs[(t >> 8) * 260 + (t & 255)] = h[((size_t)row0 << 8) + t];
    __syncthreads();

    float4 acc[4];
#pragma unroll
    for (int q = 0; q < 4; q++) acc[q] = make_float4(0.f, 0.f, 0.f, 0.f);

#pragma unroll 4
    for (int k = 0; k < IN_DIM; k++) {
        float hv = hs[row * 260 + k];
        const float4* wr = (const float4*)(Ws + k * OUT_DIM + cs);
#pragma unroll
        for (int q = 0; q < 4; q++) {
            float4 w4 = wr[q];
            acc[q].x = fmaf(hv, w4.x, acc[q].x);
            acc[q].y = fmaf(hv, w4.y, acc[q].y);
            acc[q].z = fmaf(hv, w4.z, acc[q].z);
            acc[q].w = fmaf(hv, w4.w, acc[q].w);
        }
    }

    float4* wout = (float4*)(g_Wh + (size_t)(row0 + row) * OUT_DIM + cs);
#pragma unroll
    for (int q = 0; q < 4; q++) wout[q] = acc[q];

    float s1 = 0.f, s2 = 0.f;
#pragma unroll
    for (int q = 0; q < 4; q++) {
        const float* ap = a + cs + q * 4;
        const float* bp = a + OUT_DIM + cs + q * 4;
        float v[4] = {acc[q].x, acc[q].y, acc[q].z, acc[q].w};
#pragma unroll
        for (int c = 0; c < 4; c++) { s1 = fmaf(v[c], ap[c], s1); s2 = fmaf(v[c], bp[c], s2); }
    }
    s1 += __shfl_xor_sync(~0u, s1, 1); s1 += __shfl_xor_sync(~0u, s1, 2);
    s2 += __shfl_xor_sync(~0u, s2, 1); s2 += __shfl_xor_sync(~0u, s2, 2);
    if ((tid & 3) == 0) { g_f1[row0 + row] = s1; g_f2[row0 + row] = s2; }
}

// ========== K1bc: blocks [0,256): B fragments; [256,288): exp vectors ==========
#define FRAG_BLOCKS 256
__global__ void __launch_bounds__(256) k1bc(void) {
    int bx = blockIdx.x, tid = threadIdx.x;

    if (bx < FRAG_BLOCKS) {
        __shared__ float whs[2][16 * 64];
        int half = tid >> 7, t = tid & 127;
        int kc = bx * 2 + half;
        const float4* src = (const float4*)(g_Wh + (size_t)kc * 16 * 64);
        float4* dst = (float4*)whs[half];
        dst[t] = src[t];
        dst[t + 128] = src[t + 128];
        __syncthreads();

        int p = (t >> 5) & 3, lane = t & 31;
        int lk = (lane & 3) * 2;
        int n0 = p * 16 + (lane >> 2);
        int n1 = n0 + 8;
        const float* w = whs[half];
        uint4 o;
        o.x = packh2(w[lk * 64 + n0],       w[(lk + 1) * 64 + n0]);
        o.y = packh2(w[(lk + 8) * 64 + n0], w[(lk + 9) * 64 + n0]);
        o.z = packh2(w[lk * 64 + n1],       w[(lk + 1) * 64 + n1]);
        o.w = packh2(w[(lk + 8) * 64 + n1], w[(lk + 9) * 64 + n1]);
        g_Bfrag[(kc * 4 + p) * 32 + lane] = o;
    } else {
        __shared__ float m1s[8], m2s[8], lss;
        float m1 = -1e30f, m2 = -1e30f;
        for (int i = tid; i < NN; i += 256) {
            m1 = fmaxf(m1, g_f1[i]);
            m2 = fmaxf(m2, g_f2[i]);
        }
#pragma unroll
        for (int o = 16; o; o >>= 1) {
            m1 = fmaxf(m1, __shfl_xor_sync(~0u, m1, o));
            m2 = fmaxf(m2, __shfl_xor_sync(~0u, m2, o));
        }
        if ((tid & 31) == 0) { m1s[tid >> 5] = m1; m2s[tid >> 5] = m2; }
        __syncthreads();
        if (tid == 0) {
            float a1 = m1s[0], a2 = m2s[0];
#pragma unroll
            for (int i = 1; i < 8; i++) { a1 = fmaxf(a1, m1s[i]); a2 = fmaxf(a2, m2s[i]); }
            lss = logf(49000.f) - a1 - a2;
        }
        __syncthreads();
        float ls = lss;
        int i = (bx - FRAG_BLOCKS) * 256 + tid;
        float f1 = g_f1[i], f2 = g_f2[i];
        g_EG1[i] = make_float2(expf(f1 + ls), expf(0.2f * f1 + ls));
        g_EG2[i] = make_float2(expf(f2), expf(0.2f * f2));
    }
}

// ================= K2: masked attention, HMMA + cp.async 2-stage pipeline =================
// smem bytes: EG2 [0,16384) | A ring [16384, 86016) | B ring [86016, 102400)
#define SM_A0 16384
#define SM_AST 34816          // one A stage: 8 warps * 16 rows * APITCH * 4
#define SM_B0 86016
#define SM_BST 8192
extern __shared__ char k2smraw[];
__global__ void __launch_bounds__(256, 2) k2_attn(const int* __restrict__ A) {
    float2* EG2s = (float2*)k2smraw;
    int tid = threadIdx.x, wid = tid >> 5, lane = tid & 31;
    int kb = blockIdx.x;
    int rowBase = blockIdx.y * MTILE;
    uint32_t sb = s2u(k2smraw);

    for (int i = tid; i < KSLAB; i += 256) EG2s[i] = g_EG2[kb * KSLAB + i];

    int r_lo = lane >> 2;
    int q2 = (lane & 3) * 2;
    int myrow = rowBase + wid * 16;
    float2 eg1a = g_EG1[myrow + r_lo];
    float2 eg1b = g_EG1[myrow + r_lo + 8];

    float acc[8][4];
#pragma unroll
    for (int n = 0; n < 8; n++)
#pragma unroll
        for (int c = 0; c < 4; c++) acc[n][c] = 0.f;
    float dn0 = 0.f, dn1 = 0.f;

    const int* Arow = A + (size_t)myrow * NN + kb * KSLAB;
    int ldRow = lane >> 4;                 // 0..1
    int ldSeg = (lane & 15) * 4;           // int offset 0..60
    uint32_t aWarp = sb + SM_A0 + wid * (16 * APITCH * 4);   // this warp's slice
    const uint4* bSrcBase = g_Bfrag + ((size_t)kb * 128) * 4 * 32 / 4;  // = g_Bfrag + kb*KSLAB/16*128

    // ---- stage issue helper (A: 8x16B per lane; B: 2x16B per thread) ----
#define ISSUE_STAGE(s) do {                                                       \
        int _c0 = (s) * 64;                                                       \
        uint32_t _ad = aWarp + ((s) & 1) * 0 + (((s) & 1) ? SM_AST : 0);          \
        _Pragma("unroll")                                                         \
        for (int _L = 0; _L < 8; _L++)                                            \
            cpasync16(_ad + ((_L * 2 + ldRow) * APITCH + ldSeg) * 4,              \
                      Arow + (size_t)(_L * 2 + ldRow) * NN + _c0 + ldSeg);        \
        uint32_t _bd = sb + SM_B0 + ((s) & 1) * SM_BST + tid * 16;                \
        const char* _bs = (const char*)(g_Bfrag + ((size_t)kb * 128 + (s) * 4) * 128); \
        cpasync16(_bd, _bs + tid * 16);                                           \
        cpasync16(_bd + 4096, _bs + tid * 16 + 4096);                             \
        CP_COMMIT();                                                              \
    } while (0)

    ISSUE_STAGE(0);
    ISSUE_STAGE(1);

#pragma unroll 1
    for (int it = 0; it < NIT; ++it) {
        CP_WAIT1();
        __syncthreads();

        const int* Aw = (const int*)(k2smraw + SM_A0 + (it & 1) * SM_AST) + wid * 16 * APITCH;
        const uint4* Bs = (const uint4*)(k2smraw + SM_B0 + (it & 1) * SM_BST);

#pragma unroll
        for (int ck = 0; ck < 4; ++ck) {
            int cl = it * 64 + ck * 16;
            float4 egA = *(const float4*)(&EG2s[cl + q2]);
            float4 egB = *(const float4*)(&EG2s[cl + q2 + 8]);
            int base = ck * 16 + q2;
            int2 aL0 = *(const int2*)(Aw + r_lo * APITCH + base);
            int2 aL1 = *(const int2*)(Aw + r_lo * APITCH + base + 8);
            int2 aH0 = *(const int2*)(Aw + (r_lo + 8) * APITCH + base);
            int2 aH1 = *(const int2*)(Aw + (r_lo + 8) * APITCH + base + 8);

            float w00 = (aL0.x > 0) ? fmaxf(eg1a.x * egA.x, eg1a.y * egA.y) : 0.f;
            float w01 = (aL0.y > 0) ? fmaxf(eg1a.x * egA.z, eg1a.y * egA.w) : 0.f;
            float w02 = (aL1.x > 0) ? fmaxf(eg1a.x * egB.x, eg1a.y * egB.y) : 0.f;
            float w03 = (aL1.y > 0) ? fmaxf(eg1a.x * egB.z, eg1a.y * egB.w) : 0.f;
            float w10 = (aH0.x > 0) ? fmaxf(eg1b.x * egA.x, eg1b.y * egA.y) : 0.f;
            float w11 = (aH0.y > 0) ? fmaxf(eg1b.x * egA.z, eg1b.y * egA.w) : 0.f;
            float w12 = (aH1.x > 0) ? fmaxf(eg1b.x * egB.x, eg1b.y * egB.y) : 0.f;
            float w13 = (aH1.y > 0) ? fmaxf(eg1b.x * egB.z, eg1b.y * egB.w) : 0.f;

            dn0 += (w00 + w01) + (w02 + w03);
            dn1 += (w10 + w11) + (w12 + w13);

            uint32_t a0 = packh2(w00, w01);
            uint32_t a1 = packh2(w10, w11);
            uint32_t a2 = packh2(w02, w03);
            uint32_t a3 = packh2(w12, w13);

            const uint4* Bp = Bs + (ck * 4) * 32 + lane;
            uint4 B0 = Bp[0], B1 = Bp[32], B2 = Bp[64], B3 = Bp[96];
            mma16816(acc[0], a0, a1, a2, a3, B0.x, B0.y);
            mma16816(acc[1], a0, a1, a2, a3, B0.z, B0.w);
            mma16816(acc[2], a0, a1, a2, a3, B1.x, B1.y);
            mma16816(acc[3], a0, a1, a2, a3, B1.z, B1.w);
            mma16816(acc[4], a0, a1, a2, a3, B2.x, B2.y);
            mma16816(acc[5], a0, a1, a2, a3, B2.z, B2.w);
            mma16816(acc[6], a0, a1, a2, a3, B3.x, B3.y);
            mma16816(acc[7], a0, a1, a2, a3, B3.z, B3.w);
        }
        __syncthreads();
        if (it + 2 < NIT) ISSUE_STAGE(it + 2);
        else CP_COMMIT();    // keep group accounting uniform
    }

    // denominator (fp32-exact)
    dn0 += __shfl_xor_sync(~0u, dn0, 1); dn0 += __shfl_xor_sync(~0u, dn0, 2);
    dn1 += __shfl_xor_sync(~0u, dn1, 1); dn1 += __shfl_xor_sync(~0u, dn1, 2);
    if ((lane & 3) == 0) {
        g_den[kb * NN + myrow + r_lo] = dn0;
        g_den[kb * NN + myrow + r_lo + 8] = dn1;
    }
    // numerator partials
    float* np = g_num + ((size_t)kb * NN + myrow) * OUT_DIM;
#pragma unroll
    for (int nt = 0; nt < 8; nt++) {
        int col = nt * 8 + q2;
        *(float2*)(np + (size_t)r_lo * OUT_DIM + col)       = make_float2(acc[nt][0], acc[nt][1]);
        *(float2*)(np + (size_t)(r_lo + 8) * OUT_DIM + col) = make_float2(acc[nt][2], acc[nt][3]);
    }
}

// ================= K3: reduce, normalize, elu =================
__global__ void k3_fin(float* __restrict__ out) {
    int gid = blockIdx.x * 256 + threadIdx.x;
    int base = gid * 4;
    int row = base >> 6;
    float4 s = make_float4(0.f, 0.f, 0.f, 0.f);
    float d = 0.f;
#pragma unroll
    for (int c = 0; c < KB; c++) {
        float4 v = *(const float4*)(g_num + (size_t)c * NN * OUT_DIM + base);
        s.x += v.x; s.y += v.y; s.z += v.z; s.w += v.w;
        d += g_den[c * NN + row];
    }
    float inv = 1.f / d;
    float4 o;
    o.x = s.x * inv; o.y = s.y * inv; o.z = s.z * inv; o.w = s.w * inv;
    o.x = o.x > 0.f ? o.x : expm1f(o.x);
    o.y = o.y > 0.f ? o.y : expm1f(o.y);
    o.z = o.z > 0.f ? o.z : expm1f(o.z);
    o.w = o.w > 0.f ? o.w : expm1f(o.w);
    *(float4*)(out + base) = o;
}

// ================= launch =================
extern "C" void kernel_launch(void* const* d_in, const int* in_sizes, int n_in,
                              void* d_out, int out_size) {
    const float* h = nullptr; const int* A = nullptr;
    const float* W = nullptr; const float* a = nullptr;
    for (int i = 0; i < n_in; i++) {
        if      (in_sizes[i] == NN * IN_DIM)      h = (const float*)d_in[i];
        else if (in_sizes[i] == IN_DIM * OUT_DIM) W = (const float*)d_in[i];
        else if (in_sizes[i] == 2 * OUT_DIM)      a = (const float*)d_in[i];
        else                                      A = (const int*)d_in[i];
    }
    float* out = (float*)d_out;

    const int k1_smem = (IN_DIM * OUT_DIM + 64 * 260) * (int)sizeof(float);
    cudaFuncSetAttribute(k1_wh, cudaFuncAttributeMaxDynamicSharedMemorySize, k1_smem);
    const int k2_smem = SM_B0 + 2 * SM_BST;   // 102400
    cudaFuncSetAttribute(k2_attn, cudaFuncAttributeMaxDynamicSharedMemorySize, k2_smem);

    k1_wh<<<NN / 64, 256, k1_smem>>>(h, W, a);
    k1bc<<<FRAG_BLOCKS + NN / 256, 256>>>();
    dim3 g2(KB, NN / MTILE);
    k2_attn<<<g2, 256, k2_smem>>>(A);
    k3_fin<<<(NN * OUT_DIM) / 1024, 256>>>(out);
}